// round 17
// baseline (speedup 1.0000x reference)
#include <cuda_runtime.h>
#include <cuda_fp16.h>
#include <cstdint>

#define S_LEN 4096
#define NB    4
#define DIN   512
#define DOUT  64

// Scratch (device globals = sanctioned scratch; no cudaMalloc allowed)
// Q/K: single fp16 limb, pairs along d: [b*S+s][32 u32]  (Q pre-scaled)
__device__ uint32_t g_Qh[NB * S_LEN * 32];
__device__ uint32_t g_Kh[NB * S_LEN * 32];
// V transposed, single fp16 limb, pairs along s: [b*64+e][2048 u32]
__device__ uint32_t g_Vh[NB * 64 * 2048];
// Partial outputs (only tiles 32..63 per batch use these)
__device__ float g_Opart[NB * 64 * 2 * 64 * 64];
__device__ float g_lpart[NB * 64 * 2 * 64];

// ---------------------------------------------------------------------------
// helpers
// ---------------------------------------------------------------------------
__device__ __forceinline__ float ex2(float x) {
    float r; asm("ex2.approx.f32 %0, %1;" : "=f"(r) : "f"(x)); return r;
}
// pack two floats -> f16x2
__device__ __forceinline__ uint32_t packh2(float a, float b) {
    __half2 h = __floats2half2_rn(a, b);
    return *(uint32_t*)&h;
}

// D += A*B  (m16n8k16, fp16 in, f32 accum)
#define MMAH(d, a, b0, b1)                                                   \
    asm volatile("mma.sync.aligned.m16n8k16.row.col.f32.f16.f16.f32 "        \
        "{%0,%1,%2,%3}, {%4,%5,%6,%7}, {%8,%9}, {%0,%1,%2,%3};"              \
        : "+f"((d)[0]), "+f"((d)[1]), "+f"((d)[2]), "+f"((d)[3])             \
        : "r"((a)[0]), "r"((a)[1]), "r"((a)[2]), "r"((a)[3]),                \
          "r"(b0), "r"(b1))

// Q scale: 1/sqrt(64) * log2(e)  (folded into Wq during staging)
#define QSCALE 0.18033688011112042f

// ===========================================================================
// Tensorized projection, fp16 single-pass: Y = Xh @ Wh. CTA = 256 thr,
// 128-row tile, K chunks of 64. W^T staged per-chunk straight from fp32 W
// (L2-resident; identical rounding to the old prep kernel).
// Epilogue writes single fp16 limbs: Q (scaled via W), K, V^T.
// ===========================================================================
#define PRS 36
#define XH_OFF 0
#define WH_OFF (128 * PRS)
#define PSM_U32 (WH_OFF + 64 * PRS)

__global__ __launch_bounds__(256, 2) void proj_kernel(
    const float* __restrict__ Xk, const float* __restrict__ Xv,
    const float* __restrict__ Xq, const float* __restrict__ Wq,
    const float* __restrict__ Wk, const float* __restrict__ Wv)
{
    extern __shared__ uint32_t sm[];
    const int tid  = threadIdx.x;
    const int w    = tid >> 5;
    const int lane = tid & 31;
    const int gq   = lane >> 2;
    const int tq   = lane & 3;
    const int m0   = w * 16;
    const int t    = blockIdx.x;        // 0..127
    const int mat  = blockIdx.y;        // 0=Q 1=K 2=V

    const float* __restrict__ X = (mat == 0) ? Xq : (mat == 1) ? Xk : Xv;
    const float* __restrict__ W = (mat == 0) ? Wq : (mat == 1) ? Wk : Wv;
    const float ws = (mat == 0) ? QSCALE : 1.0f;

    float oacc[8][4];
#pragma unroll
    for (int n = 0; n < 8; ++n)
#pragma unroll
        for (int k = 0; k < 4; ++k) oacc[n][k] = 0.0f;

#pragma unroll 1
    for (int c = 0; c < 8; ++c) {
        const int k0 = c * 64;
        if (c) __syncthreads();
        // stage X tile [128][64] fp16 single limb (pairs along k)
#pragma unroll
        for (int s = 0; s < 8; ++s) {
            int idx = tid + s * 256;            // 0..2047
            int r   = idx >> 4;
            int d0  = (idx & 15) << 2;
            float4 f = *(const float4*)(X + (size_t)(t * 128 + r) * DIN + k0 + d0);
            sm[XH_OFF + r * PRS + (d0 >> 1)]     = packh2(f.x, f.y);
            sm[XH_OFF + r * PRS + (d0 >> 1) + 1] = packh2(f.z, f.w);
        }
        // stage W^T tile [64e][32 k-pairs] from raw fp32 W (coalesced on e)
#pragma unroll
        for (int s = 0; s < 8; ++s) {
            int idx = tid + s * 256;            // 0..2047
            int p   = idx >> 6;                 // 0..31 (k pair)
            int e   = idx & 63;
            float w0 = W[(size_t)(k0 + 2 * p)     * DOUT + e];
            float w1 = W[(size_t)(k0 + 2 * p + 1) * DOUT + e];
            sm[WH_OFF + e * PRS + p] = packh2(w0 * ws, w1 * ws);
        }
        __syncthreads();

        uint32_t aX[4][4];
#pragma unroll
        for (int cc = 0; cc < 4; ++cc) {
            aX[cc][0] = sm[XH_OFF + (m0 + gq)     * PRS + 8 * cc + tq];
            aX[cc][1] = sm[XH_OFF + (m0 + 8 + gq) * PRS + 8 * cc + tq];
            aX[cc][2] = sm[XH_OFF + (m0 + gq)     * PRS + 8 * cc + tq + 4];
            aX[cc][3] = sm[XH_OFF + (m0 + 8 + gq) * PRS + 8 * cc + tq + 4];
        }
        // Y += Xh * Wh  (single pass)
#pragma unroll
        for (int cc = 0; cc < 4; ++cc) {
#pragma unroll
            for (int n = 0; n < 8; ++n) {
                int rb = (n * 8 + gq) * PRS + 8 * cc + tq;
                MMAH(oacc[n], aX[cc], sm[WH_OFF + rb], sm[WH_OFF + rb + 4]);
            }
        }
    }

    if (mat == 0) {
        const int row0 = t * 128 + m0 + gq;
#pragma unroll
        for (int n = 0; n < 8; ++n) {
            g_Qh[(size_t)row0 * 32 + n * 4 + tq]       = packh2(oacc[n][0], oacc[n][1]);
            g_Qh[(size_t)(row0 + 8) * 32 + n * 4 + tq] = packh2(oacc[n][2], oacc[n][3]);
        }
    } else if (mat == 1) {
        const int row0 = t * 128 + m0 + gq;
#pragma unroll
        for (int n = 0; n < 8; ++n) {
            g_Kh[(size_t)row0 * 32 + n * 4 + tq]       = packh2(oacc[n][0], oacc[n][1]);
            g_Kh[(size_t)(row0 + 8) * 32 + n * 4 + tq] = packh2(oacc[n][2], oacc[n][3]);
        }
    } else {
        uint16_t* Vh16 = (uint16_t*)g_Vh;
        const int bb = t >> 5;
        const int s0 = (t & 31) * 128 + m0 + gq;
#pragma unroll
        for (int n = 0; n < 8; ++n) {
            int e0 = n * 8 + 2 * tq;
#pragma unroll
            for (int k = 0; k < 4; ++k) {
                int e = e0 + (k & 1);
                int s = s0 + (k >> 1) * 8;
                Vh16[(size_t)(bb * 64 + e) * S_LEN + s] =
                    __half_as_ushort(__float2half_rn(oacc[n][k]));
            }
        }
    }
}

// ===========================================================================
// HMMA flash attention, pure fp16 single-limb, double-buffered K/V with a
// SINGLE __syncthreads per iter. CTA = 128 threads = 4 warps; q-tile M=64,
// kv-tile N=64. 64 MMAs/warp/iter. smem 45 KB.
// Iter j: stage next tile into buf cur^1 (LDGs hide behind MMAs), compute on
// buf cur, barrier. The barrier separates both hazard pairs across iters.
// ===========================================================================
#define RS      36
#define QH_OFF  0
#define KO(i)   (2304 + (i) * 4608)
#define VO(i)   (4608 + (i) * 4608)
#define SMEM_U32 11520

__global__ __launch_bounds__(128) void attn_kernel(float* __restrict__ out)
{
    extern __shared__ uint32_t sm[];
    const int tid  = threadIdx.x;
    const int w    = tid >> 5;
    const int lane = tid & 31;
    const int gq   = lane >> 2;
    const int tq   = lane & 3;
    const int m0   = w * 16;

    const int b   = blockIdx.y;
    const int x   = blockIdx.x;     // 0..63
    const int pr  = x >> 1;         // 0..31
    const int sub = x & 1;

    const uint4* __restrict__ Kb4 = (const uint4*)(g_Kh + (size_t)b * S_LEN * 32);
    const uint4* __restrict__ Vb4 = (const uint4*)(g_Vh + (size_t)b * 64 * 2048);

    const int nseg = sub ? 1 : 2;
#pragma unroll 1
    for (int seg = 0; seg < nseg; ++seg) {
        int t, j0, j1, part, diag, full;
        if (!sub) {
            if (seg == 0) { t = pr;      j0 = 0;       j1 = pr + 1;  part = 0; diag = 1; full = 1; }
            else          { t = 63 - pr; j0 = 0;       j1 = 32 - pr; part = 0; diag = 0; full = 0; }
        } else            { t = 63 - pr; j0 = 32 - pr; j1 = 64 - pr; part = 1; diag = 1; full = 0; }
        const int jmask = diag ? (j1 - 1) : 0x7fffffff;

        // ---- stage Q tile + first K/V tile (buf 0) ----
        const uint4* Qh4 = (const uint4*)(g_Qh + ((size_t)b * S_LEN + t * 64) * 32);
#pragma unroll
        for (int s = 0; s < 4; ++s) {
            int idx = tid + s * 128;            // 0..511 uint4
            int r   = idx >> 3;
            int p4  = idx & 7;
            *(uint4*)&sm[QH_OFF + r * RS + 4 * p4] = Qh4[idx];
            *(uint4*)&sm[KO(0) + r * RS + 4 * p4] = Kb4[(size_t)(j0 << 6) * 8 + idx];
            *(uint4*)&sm[VO(0) + r * RS + 4 * p4] = Vb4[r * 512 + (j0 << 3) + p4];
        }
        __syncthreads();

        // ---- persistent Q fragments ----
        uint32_t aQ[4][4];
#pragma unroll
        for (int c = 0; c < 4; ++c) {
            aQ[c][0] = sm[QH_OFF + (m0 + gq)     * RS + 8 * c + tq];
            aQ[c][1] = sm[QH_OFF + (m0 + 8 + gq) * RS + 8 * c + tq];
            aQ[c][2] = sm[QH_OFF + (m0 + gq)     * RS + 8 * c + tq + 4];
            aQ[c][3] = sm[QH_OFF + (m0 + 8 + gq) * RS + 8 * c + tq + 4];
        }

        float oacc[8][4];
#pragma unroll
        for (int n = 0; n < 8; ++n)
#pragma unroll
            for (int k = 0; k < 4; ++k) oacc[n][k] = 0.0f;
        float lA = 0.0f, lB = 0.0f;

        const int qrow0 = t * 64 + m0 + gq;
        const int qrow1 = qrow0 + 8;

#pragma unroll 1
        for (int j = j0; j < j1; ++j) {
            const int cur = (j - j0) & 1;
            const int KOc = KO(cur), VOc = VO(cur);

            // ---- stage NEXT tile into the other buffer (overlaps MMAs) ----
            if (j + 1 < j1) {
                const int kb2 = (j + 1) << 6;
                const int alt = cur ^ 1;
#pragma unroll
                for (int s = 0; s < 4; ++s) {
                    int idx = tid + s * 128;    // 0..511 uint4
                    int r   = idx >> 3;
                    int p4  = idx & 7;
                    *(uint4*)&sm[KO(alt) + r * RS + 4 * p4] = Kb4[(size_t)kb2 * 8 + idx];
                    *(uint4*)&sm[VO(alt) + r * RS + 4 * p4] = Vb4[r * 512 + (kb2 >> 3) + p4];
                }
            }

            // ---- S = Q K^T (single pass) ----
            float sacc[8][4];
#pragma unroll
            for (int n = 0; n < 8; ++n)
#pragma unroll
                for (int k = 0; k < 4; ++k) sacc[n][k] = 0.0f;

#pragma unroll
            for (int c = 0; c < 4; ++c) {
#pragma unroll
                for (int n = 0; n < 8; ++n) {
                    int rb = (n * 8 + gq) * RS + 8 * c + tq;
                    MMAH(sacc[n], aQ[c], sm[KOc + rb], sm[KOc + rb + 4]);
                }
            }

            // ---- P = exp2(min(S,15.5)) with causal mask; accumulate l ----
            const int kb = j << 6;
            const bool dm = (j >= jmask);
#pragma unroll
            for (int n = 0; n < 8; ++n) {
                int col0 = kb + n * 8 + 2 * tq;
                float e0 = ex2(fminf(sacc[n][0], 15.5f));
                float e1 = ex2(fminf(sacc[n][1], 15.5f));
                float e2 = ex2(fminf(sacc[n][2], 15.5f));
                float e3 = ex2(fminf(sacc[n][3], 15.5f));
                if (dm) {
                    e0 = (col0     <= qrow0) ? e0 : 0.0f;
                    e1 = (col0 + 1 <= qrow0) ? e1 : 0.0f;
                    e2 = (col0     <= qrow1) ? e2 : 0.0f;
                    e3 = (col0 + 1 <= qrow1) ? e3 : 0.0f;
                }
                lA += e0 + e1;
                lB += e2 + e3;
                sacc[n][0] = e0; sacc[n][1] = e1;
                sacc[n][2] = e2; sacc[n][3] = e3;
            }

            // ---- P fragments (single fp16) straight from S fragments ----
            uint32_t aP[4][4];
#pragma unroll
            for (int c = 0; c < 4; ++c) {
                aP[c][0] = packh2(sacc[2 * c][0],     sacc[2 * c][1]);
                aP[c][1] = packh2(sacc[2 * c][2],     sacc[2 * c][3]);
                aP[c][2] = packh2(sacc[2 * c + 1][0], sacc[2 * c + 1][1]);
                aP[c][3] = packh2(sacc[2 * c + 1][2], sacc[2 * c + 1][3]);
            }

            // ---- O += P V (single pass) ----
#pragma unroll
            for (int c = 0; c < 4; ++c) {
#pragma unroll
                for (int n = 0; n < 8; ++n) {
                    int rb = (n * 8 + gq) * RS + 8 * c + tq;
                    MMAH(oacc[n], aP[c], sm[VOc + rb], sm[VOc + rb + 4]);
                }
            }

            __syncthreads();   // the ONE barrier: orders this iter's reads
                               // before next iter's writes, and this iter's
                               // alt-buffer writes before next iter's reads
        }

        // ---- epilogue ----
        lA += __shfl_xor_sync(0xffffffffu, lA, 1);
        lA += __shfl_xor_sync(0xffffffffu, lA, 2);
        lB += __shfl_xor_sync(0xffffffffu, lB, 1);
        lB += __shfl_xor_sync(0xffffffffu, lB, 2);

        if (full) {
            float invA = __fdividef(1.0f, lA);
            float invB = __fdividef(1.0f, lB);
            float* o = out + ((size_t)b * S_LEN + t * 64) * 64;
#pragma unroll
            for (int n = 0; n < 8; ++n) {
                int e = n * 8 + 2 * tq;
                *(float2*)(o + (size_t)(m0 + gq) * 64 + e) =
                    make_float2(oacc[n][0] * invA, oacc[n][1] * invA);
                *(float2*)(o + (size_t)(m0 + 8 + gq) * 64 + e) =
                    make_float2(oacc[n][2] * invB, oacc[n][3] * invB);
            }
        } else {
            const int slot = (b * 64 + t) * 2 + part;
            if (tq == 0) {
                g_lpart[(size_t)slot * 64 + m0 + gq]     = lA;
                g_lpart[(size_t)slot * 64 + m0 + 8 + gq] = lB;
            }
            float* Od = g_Opart + (size_t)slot * 64 * 64;
#pragma unroll
            for (int n = 0; n < 8; ++n) {
                int e = n * 8 + 2 * tq;
                *(float2*)(Od + (size_t)(m0 + gq)     * 64 + e) = make_float2(oacc[n][0], oacc[n][1]);
                *(float2*)(Od + (size_t)(m0 + 8 + gq) * 64 + e) = make_float2(oacc[n][2], oacc[n][3]);
            }
        }
        __syncthreads();   // before next seg rewrites Q / buffers
    }
}

// ---------------------------------------------------------------------------
// Combine (two-part tiles 32..63 only): out = (O0 + O1) / (l0 + l1)
// 512 blocks x 256 threads, one output float4 per thread (latency-bound fix).
// ---------------------------------------------------------------------------
__global__ __launch_bounds__(256) void combine_kernel(float* __restrict__ out)
{
    const int z  = blockIdx.x;        // 0..511
    const int u  = z >> 2;            // tile unit 0..127
    const int q4 = z & 3;             // row quarter
    const int b  = u >> 5;
    const int t  = 32 + (u & 31);
    const int bt = b * 64 + t;
    const int r  = q4 * 16 + (threadIdx.x >> 4);   // 0..63
    const int c4 = threadIdx.x & 15;               // float4 column
    const float* O0 = g_Opart + (((size_t)bt * 2 + 0) * 64 + r) * 64 + c4 * 4;
    const float* O1 = g_Opart + (((size_t)bt * 2 + 1) * 64 + r) * 64 + c4 * 4;
    float l0 = g_lpart[((size_t)bt * 2 + 0) * 64 + r];
    float l1 = g_lpart[((size_t)bt * 2 + 1) * 64 + r];
    float inv = __fdividef(1.0f, l0 + l1);
    float4 a = *(const float4*)O0;
    float4 c = *(const float4*)O1;
    float4 v = make_float4((a.x + c.x) * inv, (a.y + c.y) * inv,
                           (a.z + c.z) * inv, (a.w + c.w) * inv);
    *(float4*)(out + ((size_t)bt * 64 + r) * 64 + c4 * 4) = v;
}

extern "C" void kernel_launch(void* const* d_in, const int* in_sizes, int n_in,
                              void* d_out, int out_size)
{
    (void)in_sizes; (void)n_in; (void)out_size;
    const float* key_in   = (const float*)d_in[0];
    const float* value_in = (const float*)d_in[1];
    const float* query_in = (const float*)d_in[2];
    const float* Wq       = (const float*)d_in[3];
    const float* Wk       = (const float*)d_in[4];
    const float* Wv       = (const float*)d_in[5];
    float* out = (float*)d_out;

    static int inited = 0;
    if (!inited) {
        cudaFuncSetAttribute(proj_kernel,
                             cudaFuncAttributeMaxDynamicSharedMemorySize,
                             PSM_U32 * sizeof(uint32_t));
        inited = 1;
    }

    dim3 pgrid(NB * S_LEN / 128, 3);  // (128, 3)
    proj_kernel<<<pgrid, 256, PSM_U32 * sizeof(uint32_t)>>>(
        key_in, value_in, query_in, Wq, Wk, Wv);

    dim3 agrid(64, NB);               // 256 balanced CTAs of 128 threads
    attn_kernel<<<agrid, 128, SMEM_U32 * sizeof(uint32_t)>>>(out);

    combine_kernel<<<512, 256>>>(out);
}